// round 7
// baseline (speedup 1.0000x reference)
#include <cuda_runtime.h>
#include <cuda_bf16.h>

typedef unsigned int u32;
typedef unsigned short u16;

// Problem: N=262144 tokens, C=128.
//   d_in: ve [N,128,3] f32, se [N,128], U_w[128,128], V_w[128,128],
//         W1[128,256], b1[128], W2[384,128], b2[384]
//   out: delta_v [N,128,3] then delta_s [N,128]
//
// mma.sync m16n8k16 bf16, 3-term hi/lo split, fused fragment reuse.
// Register relief: u streamed to out (RMW'd later with a); vn2/dot in regs.
// A tile has two 512B/row halves for fill/compute double buffering.
// Weight images (pre-swizzled, [256 rows hi|lo][128 cols]) in device globals:
// 0=U^T 1=V^T 2=W1^T k0 3=W1^T k1 4..6=W2^T a,b,c

__device__ __align__(16) u16 g_img[7][32768];

__host__ __device__ __forceinline__ int img_byte(int r, int c) {
    return r * 256 + ((((c >> 3) ^ (r & 7)) << 4) | ((c & 7) << 1));
}

__global__ void prep_kernel(const float* __restrict__ U, const float* __restrict__ V,
                            const float* __restrict__ W1, const float* __restrict__ W2) {
    int t = blockIdx.x * blockDim.x + threadIdx.x;
    if (t >= 7 * 32768) return;
    int img = t >> 15, e = t & 32767;
    int r = e >> 7, n = e & 127, k = r & 127;
    float val;
    switch (img) {
        case 0:  val = U[n * 128 + k]; break;
        case 1:  val = V[n * 128 + k]; break;
        case 2:  val = W1[n * 256 + k]; break;
        case 3:  val = W1[n * 256 + 128 + k]; break;
        case 4:  val = W2[n * 128 + k]; break;
        case 5:  val = W2[(128 + n) * 128 + k]; break;
        default: val = W2[(256 + n) * 128 + k]; break;
    }
    __nv_bfloat16 h = __float2bfloat16(val);
    u16 w = (r < 128) ? __bfloat16_as_ushort(h)
                      : __bfloat16_as_ushort(__float2bfloat16(val - __bfloat162float(h)));
    g_img[img][img_byte(r, n) >> 1] = w;
}

// ---------------- device helpers ----------------
__device__ __forceinline__ u32 sw_off(int r, int c) {       // c in 0..255 -> 0..511
    return ((((c >> 3) ^ (r & 7)) << 4) | ((c & 7) << 1));
}
__device__ __forceinline__ void split2(float x0, float x1, u32& hi, u32& lo) {
    __nv_bfloat16 h0 = __float2bfloat16(x0), h1 = __float2bfloat16(x1);
    __nv_bfloat16 l0 = __float2bfloat16(x0 - __bfloat162float(h0));
    __nv_bfloat16 l1 = __float2bfloat16(x1 - __bfloat162float(h1));
    hi = ((u32)__bfloat16_as_ushort(h1) << 16) | __bfloat16_as_ushort(h0);
    lo = ((u32)__bfloat16_as_ushort(l1) << 16) | __bfloat16_as_ushort(l0);
}
#define STS32(a, v)  asm volatile("st.shared.u32 [%0], %1;" :: "r"(a), "r"(v))
#define CP_COMMIT    asm volatile("cp.async.commit_group;")
#define CP_WAIT0     asm volatile("cp.async.wait_group 0;" ::: "memory")

#define LDMX4(r0,r1,r2,r3,addr) \
    asm volatile("ldmatrix.sync.aligned.m8n8.x4.shared.b16 {%0,%1,%2,%3}, [%4];" \
                 : "=r"(r0), "=r"(r1), "=r"(r2), "=r"(r3) : "r"(addr))
#define LDMX4T(r0,r1,r2,r3,addr) \
    asm volatile("ldmatrix.sync.aligned.m8n8.x4.trans.shared.b16 {%0,%1,%2,%3}, [%4];" \
                 : "=r"(r0), "=r"(r1), "=r"(r2), "=r"(r3) : "r"(addr))
#define MMA4(D, A0,A1,A2,A3, B0r,B1r) \
    asm volatile("mma.sync.aligned.m16n8k16.row.col.f32.bf16.bf16.f32 " \
                 "{%0,%1,%2,%3},{%4,%5,%6,%7},{%8,%9},{%0,%1,%2,%3};" \
                 : "+f"((D)[0]), "+f"((D)[1]), "+f"((D)[2]), "+f"((D)[3]) \
                 : "r"(A0),"r"(A1),"r"(A2),"r"(A3), "r"(B0r),"r"(B1r))

__device__ __forceinline__ void cp_img(u32 sdst, const u16* src, int t) {
    #pragma unroll
    for (int q = 0; q < 8; q++) {
        int idx = t + q * 512;
        asm volatile("cp.async.cg.shared.global [%0], [%1], 16;"
                     :: "r"(sdst + idx * 16), "l"((const char*)src + idx * 16));
    }
}

// fused 3-term GEMM: acc[m16,n32] += split(A[, cols 0..255 @ Ab+ao]) * split(B)
__device__ __forceinline__ void gemm_f(float* acc, u32 Ab, int ao, u32 Bb,
                                       int mb, int nb, int lane) {
    const int ra = mb + (lane & 15);
    const int half8 = (lane >> 4) << 3;
    const int rbl = lane & 15;
    const u32 abase = Ab + ra * 1024 + ao;
    #pragma unroll
    for (int kc = 0; kc < 8; kc++) {
        int ch = kc * 16 + half8, cl = 128 + ch;
        u32 h0,h1,h2,h3, l0,l1,l2,l3;
        LDMX4(h0,h1,h2,h3, abase + ((((ch >> 3) ^ (ra & 7)) << 4)));
        LDMX4(l0,l1,l2,l3, abase + ((((cl >> 3) ^ (ra & 7)) << 4)));
        int rbh = kc * 16 + rbl, rblo = 128 + rbh;
        #pragma unroll
        for (int np = 0; np < 2; np++) {
            int cb = nb + np * 16 + half8;
            u32 p0,p1,p2,p3, q0,q1,q2,q3;
            LDMX4T(p0,p1,p2,p3, Bb + rbh  * 256 + ((((cb >> 3) ^ (rbh  & 7)) << 4)));
            LDMX4T(q0,q1,q2,q3, Bb + rblo * 256 + ((((cb >> 3) ^ (rblo & 7)) << 4)));
            float* d0 = acc + np * 8;
            float* d1 = d0 + 4;
            MMA4(d0, h0,h1,h2,h3, p0,p1);  MMA4(d1, h0,h1,h2,h3, p2,p3);
            MMA4(d0, l0,l1,l2,l3, p0,p1);  MMA4(d1, l0,l1,l2,l3, p2,p3);
            MMA4(d0, h0,h1,h2,h3, q0,q1);  MMA4(d1, h0,h1,h2,h3, q2,q3);
        }
    }
}

// phase-A: u and v together, A fragments shared across both weight images
__device__ __forceinline__ void gemm_uv(float* ua, float* va, u32 Ab, int ao,
                                        u32 BU, u32 BV, int mb, int nb, int lane) {
    const int ra = mb + (lane & 15);
    const int half8 = (lane >> 4) << 3;
    const int rbl = lane & 15;
    const u32 abase = Ab + ra * 1024 + ao;
    #pragma unroll
    for (int kc = 0; kc < 8; kc++) {
        int ch = kc * 16 + half8, cl = 128 + ch;
        u32 h0,h1,h2,h3, l0,l1,l2,l3;
        LDMX4(h0,h1,h2,h3, abase + ((((ch >> 3) ^ (ra & 7)) << 4)));
        LDMX4(l0,l1,l2,l3, abase + ((((cl >> 3) ^ (ra & 7)) << 4)));
        int rbh = kc * 16 + rbl, rblo = 128 + rbh;
        #pragma unroll
        for (int np = 0; np < 2; np++) {
            int cb = nb + np * 16 + half8;
            u32 boffh = rbh * 256 + ((((cb >> 3) ^ (rbh & 7)) << 4));
            u32 boffl = rblo * 256 + ((((cb >> 3) ^ (rblo & 7)) << 4));
            #pragma unroll
            for (int im = 0; im < 2; im++) {
                u32 Bb = im ? BV : BU;
                float* acc = (im ? va : ua) + np * 8;
                u32 p0,p1,p2,p3, q0,q1,q2,q3;
                LDMX4T(p0,p1,p2,p3, Bb + boffh);
                LDMX4T(q0,q1,q2,q3, Bb + boffl);
                float* d1 = acc + 4;
                MMA4(acc, h0,h1,h2,h3, p0,p1);  MMA4(d1, h0,h1,h2,h3, p2,p3);
                MMA4(acc, l0,l1,l2,l3, p0,p1);  MMA4(d1, l0,l1,l2,l3, p2,p3);
                MMA4(acc, h0,h1,h2,h3, q0,q1);  MMA4(d1, h0,h1,h2,h3, q2,q3);
            }
        }
    }
}

// prefetch x_i component (16 floats per thread) into regs
__device__ __forceinline__ void prefetch_x(float* xv, const float* __restrict__ ve,
                                           long long n0, int i, int t) {
    #pragma unroll
    for (int q = 0; q < 8; q++) {
        int p = t + q * 512;
        int r = p >> 6, c0 = (p & 63) << 1;
        const float* g = ve + (n0 + r) * 384 + c0 * 3 + i;
        xv[2 * q]     = __ldg(g);
        xv[2 * q + 1] = __ldg(g + 3);
    }
}
__device__ __forceinline__ void prefetch_se(float* xv, const float* __restrict__ se,
                                            long long n0, int t) {
    #pragma unroll
    for (int q = 0; q < 8; q++) {
        int p = t + q * 512;
        int r = p >> 6, c0 = (p & 63) << 1;
        float2 v = *(const float2*)(se + (n0 + r) * 128 + c0);
        xv[2 * q] = v.x; xv[2 * q + 1] = v.y;
    }
}
// commit 16 regs -> A half (hi cols 0-127, lo cols 128-255) at Ab+ao
__device__ __forceinline__ void commit_x(u32 Ab, int ao, const float* xv, int t) {
    #pragma unroll
    for (int q = 0; q < 8; q++) {
        int p = t + q * 512;
        int r = p >> 6, c0 = (p & 63) << 1;
        u32 hi, lo;
        split2(xv[2 * q], xv[2 * q + 1], hi, lo);
        u32 base = Ab + r * 1024 + ao;
        STS32(base + sw_off(r, c0), hi);
        STS32(base + sw_off(r, 128 + c0), lo);
    }
}

// ---------------- main kernel ----------------
// smem: A @0 (64KB: two 512B halves/row), B0 @64KB, B1 @128KB -> 192KB
__global__ __launch_bounds__(512, 1)
void update_kernel(const float* __restrict__ ve, const float* __restrict__ se,
                   const float* __restrict__ b1, const float* __restrict__ b2,
                   float* __restrict__ out, int Ntok) {
    extern __shared__ __align__(128) unsigned char smraw[];
    const u32 Ab = (u32)__cvta_generic_to_shared(smraw);
    const u32 B0 = Ab + 65536, B1 = Ab + 131072;

    const int t = threadIdx.x, lane = t & 31, warp = t >> 5;
    const int mb = (warp >> 2) << 4;      // 0,16,32,48
    const int nb = (warp & 3) << 5;       // 0,32,64,96
    const int g8 = lane >> 2, tid2 = (lane & 3) << 1;
    const long long n0 = (long long)blockIdx.x * 64;

    cp_img(B0, g_img[0], t);              // U
    cp_img(B1, g_img[1], t);              // V
    CP_COMMIT;
    float xv[16];
    prefetch_x(xv, ve, n0, 0, t);
    commit_x(Ab, 0, xv, t);
    CP_WAIT0;
    __syncthreads();

    float dot[16], vn2[16];
    #pragma unroll
    for (int x = 0; x < 16; x++) { dot[x] = 0.f; vn2[x] = 0.f; }

    // ======== phase A: u_i & v_i together; u streamed to out ========
    #pragma unroll 1
    for (int i = 0; i < 3; i++) {
        if (i < 2) prefetch_x(xv, ve, n0, i + 1, t);
        else       prefetch_se(xv, se, n0, t);
        float ua[16], va[16];
        #pragma unroll
        for (int x = 0; x < 16; x++) { ua[x] = 0.f; va[x] = 0.f; }
        gemm_uv(ua, va, Ab, (i & 1) * 512, B0, B1, mb, nb, lane);
        if (i < 2) commit_x(Ab, ((i + 1) & 1) * 512, xv, t);
        #pragma unroll
        for (int x = 0; x < 16; x++) {
            dot[x] = fmaf(ua[x], va[x], dot[x]);
            vn2[x] = fmaf(va[x], va[x], vn2[x]);
        }
        #pragma unroll
        for (int nt = 0; nt < 4; nt++)    // stream u to out (final delta_v slots)
            #pragma unroll
            for (int jr = 0; jr < 2; jr++) {
                int r = mb + g8 + jr * 8;
                int c = nb + nt * 8 + tid2;
                int idx = nt * 4 + jr * 2;
                out[(n0 + r) * 384 + c * 3 + i]       = ua[idx];
                out[(n0 + r) * 384 + (c + 1) * 3 + i] = ua[idx + 1];
            }
        __syncthreads();
    }

    // ======== mvec = [se | vnorm] ========
    cp_img(B0, g_img[2], t);              // W1 k-half0
    cp_img(B1, g_img[3], t);              // W1 k-half1
    CP_COMMIT;
    commit_x(Ab, 0, xv, t);               // se -> half0
    #pragma unroll
    for (int nt = 0; nt < 4; nt++)        // vnorm -> half1
        #pragma unroll
        for (int jr = 0; jr < 2; jr++) {
            int r = mb + g8 + jr * 8;
            int c0 = nb + nt * 8 + tid2;
            int idx = nt * 4 + jr * 2;
            float s0 = sqrtf(vn2[idx] + 1e-8f);
            float s1 = sqrtf(vn2[idx + 1] + 1e-8f);
            u32 hi, lo;
            split2(s0, s1, hi, lo);
            u32 base = Ab + r * 1024 + 512;
            STS32(base + sw_off(r, c0), hi);
            STS32(base + sw_off(r, 128 + c0), lo);
        }
    CP_WAIT0;
    __syncthreads();

    // ======== MLP1 ========
    float hacc[16];
    #pragma unroll
    for (int x = 0; x < 16; x++) hacc[x] = 0.f;
    gemm_f(hacc, Ab, 0,   B0, mb, nb, lane);
    gemm_f(hacc, Ab, 512, B1, mb, nb, lane);
    __syncthreads();                      // B0/B1/A reads done
    cp_img(B0, g_img[4], t);              // W2 tile a
    cp_img(B1, g_img[5], t);              // W2 tile b
    CP_COMMIT;
    #pragma unroll
    for (int nt = 0; nt < 4; nt++)        // silu(h) -> half0
        #pragma unroll
        for (int jr = 0; jr < 2; jr++) {
            int r = mb + g8 + jr * 8;
            int c0 = nb + nt * 8 + tid2;
            int idx = nt * 4 + jr * 2;
            float z0 = hacc[idx]     + __ldg(b1 + c0);
            float z1 = hacc[idx + 1] + __ldg(b1 + c0 + 1);
            float s0 = __fdividef(z0, 1.f + __expf(-z0));
            float s1 = __fdividef(z1, 1.f + __expf(-z1));
            u32 hi, lo;
            split2(s0, s1, hi, lo);
            u32 base = Ab + r * 1024;
            STS32(base + sw_off(r, c0), hi);
            STS32(base + sw_off(r, 128 + c0), lo);
        }
    CP_WAIT0;
    __syncthreads();

    // ======== MLP2 ========
    float aacc[16];
    #pragma unroll
    for (int x = 0; x < 16; x++) aacc[x] = 0.f;
    gemm_f(aacc, Ab, 0, B0, mb, nb, lane);
    __syncthreads();                      // B0 reads done
    cp_img(B0, g_img[6], t);              // W2 tile c (behind epilogue + gemm_b)
    CP_COMMIT;

    // delta_v = (a + b2a) * u  (u lives in out, L2-resident RMW)
    #pragma unroll
    for (int nt = 0; nt < 4; nt++)
        #pragma unroll
        for (int jr = 0; jr < 2; jr++) {
            int r = mb + g8 + jr * 8;
            #pragma unroll
            for (int jc = 0; jc < 2; jc++) {
                int c = nb + nt * 8 + tid2 + jc;
                int idx = nt * 4 + jr * 2 + jc;
                float a = aacc[idx] + __ldg(b2 + c);
                float* dst = out + (n0 + r) * 384 + c * 3;
                dst[0] *= a;
                dst[1] *= a;
                dst[2] *= a;
            }
        }

    float bacc[16];
    #pragma unroll
    for (int x = 0; x < 16; x++) bacc[x] = 0.f;
    gemm_f(bacc, Ab, 0, B1, mb, nb, lane);
    CP_WAIT0;                             // W2c in B0
    __syncthreads();

    float cacc[16];
    #pragma unroll
    for (int x = 0; x < 16; x++) cacc[x] = 0.f;
    gemm_f(cacc, Ab, 0, B0, mb, nb, lane);

    float* ds = out + (long long)Ntok * 384;
    #pragma unroll
    for (int nt = 0; nt < 4; nt++)
        #pragma unroll
        for (int jr = 0; jr < 2; jr++) {
            int r = mb + g8 + jr * 8;
            int c0 = nb + nt * 8 + tid2;
            int idx = nt * 4 + jr * 2;
            float d0 = (bacc[idx]     + __ldg(b2 + 128 + c0))
                     + (cacc[idx]     + __ldg(b2 + 256 + c0)) * dot[idx];
            float d1 = (bacc[idx + 1] + __ldg(b2 + 129 + c0))
                     + (cacc[idx + 1] + __ldg(b2 + 257 + c0)) * dot[idx + 1];
            *(float2*)(ds + (n0 + r) * 128 + c0) = make_float2(d0, d1);
        }
}

extern "C" void kernel_launch(void* const* d_in, const int* in_sizes, int n_in,
                              void* d_out, int out_size) {
    const float* ve = (const float*)d_in[0];
    const float* se = (const float*)d_in[1];
    const float* Uw = (const float*)d_in[2];
    const float* Vw = (const float*)d_in[3];
    const float* W1 = (const float*)d_in[4];
    const float* b1 = (const float*)d_in[5];
    const float* W2 = (const float*)d_in[6];
    const float* b2 = (const float*)d_in[7];
    float* out = (float*)d_out;

    const int N = in_sizes[0] / 384;        // 262144
    const int smem_bytes = 196608;          // 192 KB

    cudaFuncSetAttribute(update_kernel, cudaFuncAttributeMaxDynamicSharedMemorySize, smem_bytes);

    prep_kernel<<<448, 512>>>(Uw, Vw, W1, W2);
    update_kernel<<<N / 64, 512, smem_bytes>>>(ve, se, b1, b2, out, N);
}